// round 5
// baseline (speedup 1.0000x reference)
#include <cuda_runtime.h>
#include <math.h>
#include <stdint.h>

#define T 2048
#define H 1024
#define M 512
#define E 32
#define TOPK 4
#define NROWS (T * TOPK)
#define PROWS (NROWS + 128)

// ------------------------- static device scratch ---------------------------
__device__ int   g_count[E];
__device__ int   g_off[E];
__device__ int   g_typre[E + 1];
__device__ int   g_tok[E * T];
__device__ float g_wt[E * T];
__device__ float g_hbuf[(size_t)PROWS * M];
__device__ float g_part[(size_t)NROWS * H];

// ------------------------- helpers -----------------------------------------
__device__ __forceinline__ uint32_t ftu(float f) {
    uint32_t u; asm("cvt.rna.tf32.f32 %0, %1;" : "=r"(u) : "f"(f)); return u;
}
__device__ __forceinline__ uint4 cvt4(float4 v) {
    uint4 o; o.x = ftu(v.x); o.y = ftu(v.y); o.z = ftu(v.z); o.w = ftu(v.w); return o;
}
__device__ __forceinline__ void mma_tf32(float* c, const uint32_t* a, uint32_t b0, uint32_t b1) {
    asm volatile("mma.sync.aligned.m16n8k8.row.col.f32.tf32.tf32.f32 "
        "{%0,%1,%2,%3}, {%4,%5,%6,%7}, {%8,%9}, {%0,%1,%2,%3};"
        : "+f"(c[0]), "+f"(c[1]), "+f"(c[2]), "+f"(c[3])
        : "r"(a[0]), "r"(a[1]), "r"(a[2]), "r"(a[3]), "r"(b0), "r"(b1));
}

// paired-k layout: row stride 40 words; within row, k -> k8*8 + (k&3)*2 + ((k>>2)&1)
#define RSTRIDE 40
// scatter-store one float4 (k values jj4..jj4+3, jj4 multiple of 4)
__device__ __forceinline__ void sts_pk(uint32_t* arr, int rr, int jj4, uint4 v) {
    int base = rr * RSTRIDE + ((jj4 >> 3) << 3) + ((jj4 >> 2) & 1);
    arr[base]     = v.x;
    arr[base + 2] = v.y;
    arr[base + 4] = v.z;
    arr[base + 6] = v.w;
}

// ------------------------- small kernels -----------------------------------
__global__ void zero_counts() { if (threadIdx.x < E) g_count[threadIdx.x] = 0; }

__global__ void router_kernel(const float* __restrict__ x,
                              const float* __restrict__ gate_w) {
    __shared__ float xs[H];
    __shared__ float logits[E];
    int t = blockIdx.x;
    const float* xr = x + (size_t)t * H;
    for (int i = threadIdx.x; i < H; i += blockDim.x) xs[i] = xr[i];
    __syncthreads();
    int warp = threadIdx.x >> 5, lane = threadIdx.x & 31;
    for (int e = warp; e < E; e += 4) {
        const float* w = gate_w + (size_t)e * H;
        float s = 0.f;
        for (int i = lane; i < H; i += 32) s += xs[i] * w[i];
        #pragma unroll
        for (int o = 16; o > 0; o >>= 1) s += __shfl_xor_sync(0xffffffffu, s, o);
        if (lane == 0) logits[e] = s;
    }
    __syncthreads();
    if (threadIdx.x == 0) {
        int ids[TOPK]; float vals[TOPK];
        unsigned used = 0;
        for (int k = 0; k < TOPK; k++) {
            float best = -INFINITY; int bi = 0;
            for (int e = 0; e < E; e++)
                if (!((used >> e) & 1u) && logits[e] > best) { best = logits[e]; bi = e; }
            used |= (1u << bi); ids[k] = bi; vals[k] = best;
        }
        float mx = vals[0], se = 0.f, w4[TOPK];
        for (int k = 0; k < TOPK; k++) { w4[k] = expf(vals[k] - mx); se += w4[k]; }
        float inv = 1.0f / se;
        for (int k = 0; k < TOPK; k++) {
            int e = ids[k];
            int pos = atomicAdd(&g_count[e], 1);
            g_tok[e * T + pos] = t * TOPK + k;
            g_wt[e * T + pos] = w4[k] * inv;
        }
    }
}

__global__ void scan_kernel() {
    int lane = threadIdx.x;
    int c = g_count[lane];
    int ex = c;
    #pragma unroll
    for (int o = 1; o < 32; o <<= 1) {
        int v = __shfl_up_sync(0xffffffffu, ex, o);
        if (lane >= o) ex += v;
    }
    g_off[lane] = ex - c;
    int ty = (c + 127) >> 7;
    int tp = ty;
    #pragma unroll
    for (int o = 1; o < 32; o <<= 1) {
        int v = __shfl_up_sync(0xffffffffu, tp, o);
        if (lane >= o) tp += v;
    }
    g_typre[lane] = tp - ty;
    if (lane == 31) g_typre[E] = tp;
}

// ------------------------- gate/up mma GEMM --------------------------------
// persistent; 512 threads, 16 warps 4x4; block 128x128; warp 32x32 (G+U)
#define GU_TILEW (128 * RSTRIDE)           // 5120 words per array
#define GU_SMEMB (2 * 3 * GU_TILEW * 4)    // 122880 bytes

__global__ void __launch_bounds__(512, 1)
gateup_mma(const float* __restrict__ x,
           const float* __restrict__ wg, const float* __restrict__ wu) {
    extern __shared__ uint32_t sm[];
    __shared__ int   styp[E + 1];
    __shared__ int   said_s[128];
    __shared__ float swt_s[128];

    int tid = threadIdx.x, lane = tid & 31, wid = tid >> 5;
    int gid = lane >> 2, tig = lane & 3;
    int wm = wid & 3, wn = wid >> 2;

    if (tid <= E) styp[tid] = g_typre[tid];
    __syncthreads();
    int totalW = styp[E] * 4;

    int rr0 = tid >> 3;
    int rr1 = (tid + 512) >> 3;
    int jj4 = (tid & 7) * 4;

    for (int w = blockIdx.x; w < totalW; w += gridDim.x) {
        int ytl = w >> 2, xt = w & 3;
        int e = 0;
        while (styp[e + 1] <= ytl) e++;
        int t0 = (ytl - styp[e]) * 128;
        int m0 = xt * 128;
        int n  = g_count[e];
        int gbase = g_off[e] + t0;

        __syncthreads();
        if (tid < 128) {
            int slot = t0 + tid;
            bool v = slot < n;
            said_s[tid] = v ? g_tok[e * T + slot] : -1;
            swt_s[tid]  = v ? g_wt[e * T + slot] : 0.f;
        }
        __syncthreads();

        const float* wgb = wg + ((size_t)e * M + m0) * H;
        const float* wub = wu + ((size_t)e * M + m0) * H;

        float accG[2][4][4], accU[2][4][4];
        #pragma unroll
        for (int i = 0; i < 2; i++)
            #pragma unroll
            for (int j = 0; j < 4; j++)
                #pragma unroll
                for (int q = 0; q < 4; q++) { accG[i][j][q] = 0.f; accU[i][j][q] = 0.f; }

        uint4 pa[2], pg[2], pu[2];
        int aid0 = said_s[rr0], aid1 = said_s[rr1];

        auto ldc = [&](int c) {
            int ko = c * 32;
            pa[0] = (aid0 >= 0) ? cvt4(*(const float4*)(x + (size_t)(aid0 >> 2) * H + ko + jj4))
                                : make_uint4(0, 0, 0, 0);
            pa[1] = (aid1 >= 0) ? cvt4(*(const float4*)(x + (size_t)(aid1 >> 2) * H + ko + jj4))
                                : make_uint4(0, 0, 0, 0);
            pg[0] = cvt4(*(const float4*)(wgb + (size_t)rr0 * H + ko + jj4));
            pg[1] = cvt4(*(const float4*)(wgb + (size_t)rr1 * H + ko + jj4));
            pu[0] = cvt4(*(const float4*)(wub + (size_t)rr0 * H + ko + jj4));
            pu[1] = cvt4(*(const float4*)(wub + (size_t)rr1 * H + ko + jj4));
        };
        auto sts = [&](int s) {
            uint32_t* A = sm + s * 3 * GU_TILEW;
            uint32_t* G = A + GU_TILEW;
            uint32_t* U = G + GU_TILEW;
            sts_pk(A, rr0, jj4, pa[0]); sts_pk(A, rr1, jj4, pa[1]);
            sts_pk(G, rr0, jj4, pg[0]); sts_pk(G, rr1, jj4, pg[1]);
            sts_pk(U, rr0, jj4, pu[0]); sts_pk(U, rr1, jj4, pu[1]);
        };
        auto compute = [&](int s) {
            const uint32_t* A = sm + s * 3 * GU_TILEW;
            const uint32_t* G = A + GU_TILEW;
            const uint32_t* U = G + GU_TILEW;
            #pragma unroll
            for (int k8 = 0; k8 < 4; k8++) {
                int kw = k8 * 8 + tig * 2;
                uint32_t a[2][4];
                #pragma unroll
                for (int mt = 0; mt < 2; mt++) {
                    int r0 = wm * 32 + mt * 16 + gid;
                    uint2 lo = *(const uint2*)(A + r0 * RSTRIDE + kw);
                    uint2 hi = *(const uint2*)(A + (r0 + 8) * RSTRIDE + kw);
                    a[mt][0] = lo.x; a[mt][1] = hi.x; a[mt][2] = lo.y; a[mt][3] = hi.y;
                }
                #pragma unroll
                for (int nt = 0; nt < 4; nt++) {
                    int nb = wn * 32 + nt * 8 + gid;
                    uint2 bg = *(const uint2*)(G + nb * RSTRIDE + kw);
                    uint2 bu = *(const uint2*)(U + nb * RSTRIDE + kw);
                    #pragma unroll
                    for (int mt = 0; mt < 2; mt++) {
                        mma_tf32(accG[mt][nt], a[mt], bg.x, bg.y);
                        mma_tf32(accU[mt][nt], a[mt], bu.x, bu.y);
                    }
                }
            }
        };

        const int NC = H / 32;   // 32
        ldc(0); sts(0);
        __syncthreads();
        ldc(1);
        for (int c = 0; c < NC; c++) {
            compute(c & 1);
            if (c + 1 < NC) sts((c + 1) & 1);
            __syncthreads();
            if (c + 2 < NC) ldc(c + 2);
        }

        // epilogue
        #pragma unroll
        for (int mt = 0; mt < 2; mt++) {
            #pragma unroll
            for (int rh = 0; rh < 2; rh++) {
                int r = wm * 32 + mt * 16 + gid + rh * 8;
                int aid = said_s[r];
                if (aid < 0) continue;
                float wv = swt_s[r];
                float* hp = g_hbuf + (size_t)(gbase + r) * M + m0 + wn * 32;
                #pragma unroll
                for (int nt = 0; nt < 4; nt++) {
                    float g0 = accG[mt][nt][rh * 2 + 0];
                    float g1 = accG[mt][nt][rh * 2 + 1];
                    float u0 = accU[mt][nt][rh * 2 + 0];
                    float u1 = accU[mt][nt][rh * 2 + 1];
                    float2 o;
                    o.x = (g0 / (1.f + __expf(-g0))) * u0 * wv;
                    o.y = (g1 / (1.f + __expf(-g1))) * u1 * wv;
                    *(float2*)(hp + nt * 8 + tig * 2) = o;
                }
            }
        }
    }
}

// ------------------------- down mma GEMM -----------------------------------
// persistent; 256 threads, 8 warps 2x4; block 128x128; warp 64x32
#define DN_TILEW (128 * RSTRIDE)           // 5120 words
#define DN_SMEMB (2 * 2 * DN_TILEW * 4)    // 81920 bytes

__global__ void __launch_bounds__(256, 2)
down_mma(const float* __restrict__ wd) {
    extern __shared__ uint32_t sm[];
    __shared__ int styp[E + 1];
    __shared__ int said_s[128];

    int tid = threadIdx.x, lane = tid & 31, wid = tid >> 5;
    int gid = lane >> 2, tig = lane & 3;
    int wm = wid & 1, wn = wid >> 1;

    if (tid <= E) styp[tid] = g_typre[tid];
    __syncthreads();
    int totalW = styp[E] * 8;

    int rr[4], jj4 = (tid & 7) * 4;
    #pragma unroll
    for (int i = 0; i < 4; i++) rr[i] = (tid + i * 256) >> 3;

    for (int w = blockIdx.x; w < totalW; w += gridDim.x) {
        int ytl = w >> 3, xt = w & 7;
        int e = 0;
        while (styp[e + 1] <= ytl) e++;
        int t0 = (ytl - styp[e]) * 128;
        int h0 = xt * 128;
        int n  = g_count[e];
        int gbase = g_off[e] + t0;

        __syncthreads();
        if (tid < 128) {
            int slot = t0 + tid;
            said_s[tid] = (slot < n) ? g_tok[e * T + slot] : -1;
        }
        __syncthreads();

        const float* ab  = g_hbuf + (size_t)gbase * M;
        const float* wdb = wd + ((size_t)e * H + h0) * M;

        float acc[4][4][4];
        #pragma unroll
        for (int i = 0; i < 4; i++)
            #pragma unroll
            for (int j = 0; j < 4; j++)
                #pragma unroll
                for (int q = 0; q < 4; q++) acc[i][j][q] = 0.f;

        uint4 pa[4], pw[4];
        auto ldc = [&](int c) {
            int ko = c * 32;
            #pragma unroll
            for (int i = 0; i < 4; i++) {
                pa[i] = cvt4(*(const float4*)(ab  + (size_t)rr[i] * M + ko + jj4));
                pw[i] = cvt4(*(const float4*)(wdb + (size_t)rr[i] * M + ko + jj4));
            }
        };
        auto sts = [&](int s) {
            uint32_t* A = sm + s * 2 * DN_TILEW;
            uint32_t* W = A + DN_TILEW;
            #pragma unroll
            for (int i = 0; i < 4; i++) {
                sts_pk(A, rr[i], jj4, pa[i]);
                sts_pk(W, rr[i], jj4, pw[i]);
            }
        };
        auto compute = [&](int s) {
            const uint32_t* A = sm + s * 2 * DN_TILEW;
            const uint32_t* W = A + DN_TILEW;
            #pragma unroll
            for (int k8 = 0; k8 < 4; k8++) {
                int kw = k8 * 8 + tig * 2;
                uint32_t a[4][4];
                #pragma unroll
                for (int mt = 0; mt < 4; mt++) {
                    int r0 = wm * 64 + mt * 16 + gid;
                    uint2 lo = *(const uint2*)(A + r0 * RSTRIDE + kw);
                    uint2 hi = *(const uint2*)(A + (r0 + 8) * RSTRIDE + kw);
                    a[mt][0] = lo.x; a[mt][1] = hi.x; a[mt][2] = lo.y; a[mt][3] = hi.y;
                }
                #pragma unroll
                for (int nt = 0; nt < 4; nt++) {
                    int nb = wn * 32 + nt * 8 + gid;
                    uint2 b = *(const uint2*)(W + nb * RSTRIDE + kw);
                    #pragma unroll
                    for (int mt = 0; mt < 4; mt++)
                        mma_tf32(acc[mt][nt], a[mt], b.x, b.y);
                }
            }
        };

        const int NC = M / 32;   // 16
        ldc(0); sts(0);
        __syncthreads();
        ldc(1);
        for (int c = 0; c < NC; c++) {
            compute(c & 1);
            if (c + 1 < NC) sts((c + 1) & 1);
            __syncthreads();
            if (c + 2 < NC) ldc(c + 2);
        }

        #pragma unroll
        for (int mt = 0; mt < 4; mt++) {
            #pragma unroll
            for (int rh = 0; rh < 2; rh++) {
                int r = wm * 64 + mt * 16 + gid + rh * 8;
                int aid = said_s[r];
                if (aid < 0) continue;
                float* op = g_part + (size_t)aid * H + h0 + wn * 32;
                #pragma unroll
                for (int nt = 0; nt < 4; nt++) {
                    float2 o;
                    o.x = acc[mt][nt][rh * 2 + 0];
                    o.y = acc[mt][nt][rh * 2 + 1];
                    *(float2*)(op + nt * 8 + tig * 2) = o;
                }
            }
        }
    }
}

// ------------------------- final reduce ------------------------------------
__global__ void reduce_kernel(float* __restrict__ out) {
    int i = blockIdx.x * 256 + threadIdx.x;
    int t = i >> 8;
    int h4 = i & 255;
    const float4* p = (const float4*)(g_part + (size_t)t * 4 * H) + h4;
    float4 a = p[0], b = p[256], c = p[512], d = p[768];
    float4 o;
    o.x = a.x + b.x + c.x + d.x;
    o.y = a.y + b.y + c.y + d.y;
    o.z = a.z + b.z + c.z + d.z;
    o.w = a.w + b.w + c.w + d.w;
    ((float4*)out)[i] = o;
}

// ------------------------- launcher ----------------------------------------
extern "C" void kernel_launch(void* const* d_in, const int* in_sizes, int n_in,
                              void* d_out, int out_size) {
    const float* x      = (const float*)d_in[0];
    const float* gate_w = (const float*)d_in[1];
    const float* w_gate = (const float*)d_in[2];
    const float* w_up   = (const float*)d_in[3];
    const float* w_down = (const float*)d_in[4];
    float* out = (float*)d_out;

    cudaFuncSetAttribute(gateup_mma, cudaFuncAttributeMaxDynamicSharedMemorySize, GU_SMEMB);
    cudaFuncSetAttribute(down_mma,   cudaFuncAttributeMaxDynamicSharedMemorySize, DN_SMEMB);

    zero_counts<<<1, 32>>>();
    router_kernel<<<T, 128>>>(x, gate_w);
    scan_kernel<<<1, 32>>>();
    gateup_mma<<<148, 512, GU_SMEMB>>>(x, w_gate, w_up);
    down_mma<<<296, 256, DN_SMEMB>>>(w_down);
    reduce_kernel<<<T * H / 4 / 256, 256>>>(out);
}

// round 6
// speedup vs baseline: 1.3986x; 1.3986x over previous
#include <cuda_runtime.h>
#include <math.h>
#include <stdint.h>

#define T 2048
#define H 1024
#define M 512
#define E 32
#define TOPK 4
#define NROWS (T * TOPK)
#define PROWS (NROWS + 128)

// ------------------------- static device scratch ---------------------------
__device__ int   g_count[E];
__device__ int   g_off[E];
__device__ int   g_typre[E + 1];    // prefix of ceil(count/128)
__device__ int   g_tok[E * T];
__device__ float g_wt[E * T];
__device__ float g_hbuf[(size_t)PROWS * M];
__device__ float g_part[(size_t)NROWS * H];

// ------------------------- helpers -----------------------------------------
__device__ __forceinline__ uint32_t ftu(float f) {
    uint32_t u; asm("cvt.rna.tf32.f32 %0, %1;" : "=r"(u) : "f"(f)); return u;
}
__device__ __forceinline__ uint4 cvt4(float4 v) {
    uint4 o; o.x = ftu(v.x); o.y = ftu(v.y); o.z = ftu(v.z); o.w = ftu(v.w); return o;
}
__device__ __forceinline__ void mma_tf32(float* c, const uint32_t* a, uint32_t b0, uint32_t b1) {
    asm volatile("mma.sync.aligned.m16n8k8.row.col.f32.tf32.tf32.f32 "
        "{%0,%1,%2,%3}, {%4,%5,%6,%7}, {%8,%9}, {%0,%1,%2,%3};"
        : "+f"(c[0]), "+f"(c[1]), "+f"(c[2]), "+f"(c[3])
        : "r"(a[0]), "r"(a[1]), "r"(a[2]), "r"(a[3]), "r"(b0), "r"(b1));
}

// ------------------------- small kernels -----------------------------------
__global__ void zero_counts() { if (threadIdx.x < E) g_count[threadIdx.x] = 0; }

__global__ void router_kernel(const float* __restrict__ x,
                              const float* __restrict__ gate_w) {
    __shared__ float xs[H];
    __shared__ float logits[E];
    int t = blockIdx.x;
    const float* xr = x + (size_t)t * H;
    for (int i = threadIdx.x; i < H; i += blockDim.x) xs[i] = xr[i];
    __syncthreads();
    int warp = threadIdx.x >> 5, lane = threadIdx.x & 31;
    for (int e = warp; e < E; e += 4) {
        const float* w = gate_w + (size_t)e * H;
        float s = 0.f;
        for (int i = lane; i < H; i += 32) s += xs[i] * w[i];
        #pragma unroll
        for (int o = 16; o > 0; o >>= 1) s += __shfl_xor_sync(0xffffffffu, s, o);
        if (lane == 0) logits[e] = s;
    }
    __syncthreads();
    if (threadIdx.x == 0) {
        int ids[TOPK]; float vals[TOPK];
        unsigned used = 0;
        for (int k = 0; k < TOPK; k++) {
            float best = -INFINITY; int bi = 0;
            for (int e = 0; e < E; e++)
                if (!((used >> e) & 1u) && logits[e] > best) { best = logits[e]; bi = e; }
            used |= (1u << bi); ids[k] = bi; vals[k] = best;
        }
        float mx = vals[0], se = 0.f, w4[TOPK];
        for (int k = 0; k < TOPK; k++) { w4[k] = expf(vals[k] - mx); se += w4[k]; }
        float inv = 1.0f / se;
        for (int k = 0; k < TOPK; k++) {
            int e = ids[k];
            int pos = atomicAdd(&g_count[e], 1);
            g_tok[e * T + pos] = t * TOPK + k;
            g_wt[e * T + pos] = w4[k] * inv;
        }
    }
}

__global__ void scan_kernel() {
    int lane = threadIdx.x;
    int c = g_count[lane];
    int ex = c;
    #pragma unroll
    for (int o = 1; o < 32; o <<= 1) {
        int v = __shfl_up_sync(0xffffffffu, ex, o);
        if (lane >= o) ex += v;
    }
    g_off[lane] = ex - c;
    int ty = (c + 127) >> 7;
    int tp = ty;
    #pragma unroll
    for (int o = 1; o < 32; o <<= 1) {
        int v = __shfl_up_sync(0xffffffffu, tp, o);
        if (lane >= o) tp += v;
    }
    g_typre[lane] = tp - ty;
    if (lane == 31) g_typre[E] = tp;
}

// ------------------------- gate/up mma GEMM --------------------------------
// persistent; 256 threads, 8 warps 4x2; block 128 rows x 64 m-cols;
// warp tile 32x32 carrying BOTH gate and up; K chunk 32; stride 36
#define GU_STRIDE 36
#define GU_STAGEW (256 * GU_STRIDE)        // 128 A + 64 G + 64 U rows = 9216 words
#define GU_SMEMB  (2 * GU_STAGEW * 4)      // 73728 bytes

__global__ void __launch_bounds__(256, 2)
gateup_mma(const float* __restrict__ x,
           const float* __restrict__ wg, const float* __restrict__ wu) {
    extern __shared__ uint32_t sm[];
    __shared__ int   styp[E + 1];
    __shared__ int   said_s[128];
    __shared__ float swt_s[128];

    int tid = threadIdx.x, lane = tid & 31, wid = tid >> 5;
    int gid = lane >> 2, tig = lane & 3;
    int wm = wid & 3, wn = wid >> 2;      // 4 row-groups x 2 col-groups

    if (tid <= E) styp[tid] = g_typre[tid];
    __syncthreads();
    int totalW = styp[E] * 8;             // M/64 = 8 col tiles

    int rrA[4], rrB0, rrB1, jj4 = (tid & 7) * 4;
    #pragma unroll
    for (int i = 0; i < 4; i++) rrA[i] = (tid + i * 256) >> 3;   // 0..127
    rrB0 = tid >> 3;                      // 0..31
    rrB1 = (tid + 256) >> 3;              // 32..63

    for (int w = blockIdx.x; w < totalW; w += gridDim.x) {
        int ytl = w >> 3, xt = w & 7;
        int e = 0;
        while (styp[e + 1] <= ytl) e++;
        int t0 = (ytl - styp[e]) * 128;
        int m0 = xt * 64;
        int n  = g_count[e];
        int gbase = g_off[e] + t0;

        __syncthreads();
        if (tid < 128) {
            int slot = t0 + tid;
            bool v = slot < n;
            said_s[tid] = v ? g_tok[e * T + slot] : -1;
            swt_s[tid]  = v ? g_wt[e * T + slot] : 0.f;
        }
        __syncthreads();

        const float* wgb = wg + ((size_t)e * M + m0) * H;
        const float* wub = wu + ((size_t)e * M + m0) * H;

        float accG[2][4][4], accU[2][4][4];
        #pragma unroll
        for (int i = 0; i < 2; i++)
            #pragma unroll
            for (int j = 0; j < 4; j++)
                #pragma unroll
                for (int q = 0; q < 4; q++) { accG[i][j][q] = 0.f; accU[i][j][q] = 0.f; }

        int aidv[4];
        #pragma unroll
        for (int i = 0; i < 4; i++) aidv[i] = said_s[rrA[i]];

        uint4 pa[4], pg[2], pu[2];
        auto ldc = [&](int c) {
            int ko = c * 32;
            #pragma unroll
            for (int i = 0; i < 4; i++)
                pa[i] = (aidv[i] >= 0)
                    ? cvt4(*(const float4*)(x + (size_t)(aidv[i] >> 2) * H + ko + jj4))
                    : make_uint4(0, 0, 0, 0);
            pg[0] = cvt4(*(const float4*)(wgb + (size_t)rrB0 * H + ko + jj4));
            pg[1] = cvt4(*(const float4*)(wgb + (size_t)rrB1 * H + ko + jj4));
            pu[0] = cvt4(*(const float4*)(wub + (size_t)rrB0 * H + ko + jj4));
            pu[1] = cvt4(*(const float4*)(wub + (size_t)rrB1 * H + ko + jj4));
        };
        auto sts = [&](int s) {
            uint32_t* A = sm + s * GU_STAGEW;
            uint32_t* G = A + 128 * GU_STRIDE;
            uint32_t* U = G + 64 * GU_STRIDE;
            #pragma unroll
            for (int i = 0; i < 4; i++)
                *(uint4*)(A + rrA[i] * GU_STRIDE + jj4) = pa[i];
            *(uint4*)(G + rrB0 * GU_STRIDE + jj4) = pg[0];
            *(uint4*)(G + rrB1 * GU_STRIDE + jj4) = pg[1];
            *(uint4*)(U + rrB0 * GU_STRIDE + jj4) = pu[0];
            *(uint4*)(U + rrB1 * GU_STRIDE + jj4) = pu[1];
        };
        auto compute = [&](int s) {
            const uint32_t* A = sm + s * GU_STAGEW;
            const uint32_t* G = A + 128 * GU_STRIDE;
            const uint32_t* U = G + 64 * GU_STRIDE;
            #pragma unroll
            for (int k8 = 0; k8 < 4; k8++) {
                int k0 = k8 * 8;
                uint32_t a[2][4];
                #pragma unroll
                for (int mt = 0; mt < 2; mt++) {
                    int r0 = wm * 32 + mt * 16 + gid;
                    a[mt][0] = A[r0 * GU_STRIDE + k0 + tig];
                    a[mt][1] = A[(r0 + 8) * GU_STRIDE + k0 + tig];
                    a[mt][2] = A[r0 * GU_STRIDE + k0 + tig + 4];
                    a[mt][3] = A[(r0 + 8) * GU_STRIDE + k0 + tig + 4];
                }
                #pragma unroll
                for (int nt = 0; nt < 4; nt++) {
                    int nb = wn * 32 + nt * 8 + gid;
                    uint32_t bg0 = G[nb * GU_STRIDE + k0 + tig];
                    uint32_t bg1 = G[nb * GU_STRIDE + k0 + tig + 4];
                    uint32_t bu0 = U[nb * GU_STRIDE + k0 + tig];
                    uint32_t bu1 = U[nb * GU_STRIDE + k0 + tig + 4];
                    #pragma unroll
                    for (int mt = 0; mt < 2; mt++) {
                        mma_tf32(accG[mt][nt], a[mt], bg0, bg1);
                        mma_tf32(accU[mt][nt], a[mt], bu0, bu1);
                    }
                }
            }
        };

        const int NC = H / 32;   // 32
        ldc(0); sts(0);
        __syncthreads();
        for (int c = 0; c < NC; c++) {
            int s = c & 1;
            if (c + 1 < NC) ldc(c + 1);
            compute(s);
            __syncthreads();
            if (c + 1 < NC) { sts(s ^ 1); __syncthreads(); }
        }

        // epilogue: h = silu(gate)*up*route_w
        #pragma unroll
        for (int mt = 0; mt < 2; mt++) {
            #pragma unroll
            for (int rh = 0; rh < 2; rh++) {
                int r = wm * 32 + mt * 16 + gid + rh * 8;
                int aid = said_s[r];
                if (aid < 0) continue;
                float wv = swt_s[r];
                float* hp = g_hbuf + (size_t)(gbase + r) * M + m0 + wn * 32;
                #pragma unroll
                for (int nt = 0; nt < 4; nt++) {
                    float g0 = accG[mt][nt][rh * 2 + 0];
                    float g1 = accG[mt][nt][rh * 2 + 1];
                    float u0 = accU[mt][nt][rh * 2 + 0];
                    float u1 = accU[mt][nt][rh * 2 + 1];
                    float2 o;
                    o.x = (g0 / (1.f + __expf(-g0))) * u0 * wv;
                    o.y = (g1 / (1.f + __expf(-g1))) * u1 * wv;
                    *(float2*)(hp + nt * 8 + tig * 2) = o;
                }
            }
        }
    }
}

// ------------------------- down mma GEMM (R4, unchanged) -------------------
#define DN_STRIDE 36
#define DN_TILEW (128 * DN_STRIDE)
#define DN_SMEMB (2 * 2 * DN_TILEW * 4)    // 73728 bytes

__global__ void __launch_bounds__(256, 2)
down_mma(const float* __restrict__ wd) {
    extern __shared__ uint32_t sm[];
    __shared__ int styp[E + 1];
    __shared__ int said_s[128];

    int tid = threadIdx.x, lane = tid & 31, wid = tid >> 5;
    int gid = lane >> 2, tig = lane & 3;
    int wm = wid & 1, wn = wid >> 1;

    if (tid <= E) styp[tid] = g_typre[tid];
    __syncthreads();
    int totalW = styp[E] * 8;

    int rr[4], jj4 = (tid & 7) * 4;
    #pragma unroll
    for (int i = 0; i < 4; i++) rr[i] = (tid + i * 256) >> 3;

    for (int w = blockIdx.x; w < totalW; w += gridDim.x) {
        int ytl = w >> 3, xt = w & 7;
        int e = 0;
        while (styp[e + 1] <= ytl) e++;
        int t0 = (ytl - styp[e]) * 128;
        int h0 = xt * 128;
        int n  = g_count[e];
        int gbase = g_off[e] + t0;

        __syncthreads();
        if (tid < 128) {
            int slot = t0 + tid;
            said_s[tid] = (slot < n) ? g_tok[e * T + slot] : -1;
        }
        __syncthreads();

        const float* ab  = g_hbuf + (size_t)gbase * M;
        const float* wdb = wd + ((size_t)e * H + h0) * M;

        float acc[4][4][4];
        #pragma unroll
        for (int i = 0; i < 4; i++)
            #pragma unroll
            for (int j = 0; j < 4; j++)
                #pragma unroll
                for (int q = 0; q < 4; q++) acc[i][j][q] = 0.f;

        uint4 pa[4], pw[4];
        auto ldc = [&](int c) {
            int ko = c * 32;
            #pragma unroll
            for (int i = 0; i < 4; i++) {
                pa[i] = cvt4(*(const float4*)(ab  + (size_t)rr[i] * M + ko + jj4));
                pw[i] = cvt4(*(const float4*)(wdb + (size_t)rr[i] * M + ko + jj4));
            }
        };
        auto sts = [&](int s) {
            uint32_t* A = sm + s * 2 * DN_TILEW;
            uint32_t* W = A + DN_TILEW;
            #pragma unroll
            for (int i = 0; i < 4; i++) {
                *(uint4*)(A + rr[i] * DN_STRIDE + jj4) = pa[i];
                *(uint4*)(W + rr[i] * DN_STRIDE + jj4) = pw[i];
            }
        };
        auto compute = [&](int s) {
            const uint32_t* A = sm + s * 2 * DN_TILEW;
            const uint32_t* W = A + DN_TILEW;
            #pragma unroll
            for (int k8 = 0; k8 < 4; k8++) {
                int k0 = k8 * 8;
                uint32_t a[4][4];
                #pragma unroll
                for (int mt = 0; mt < 4; mt++) {
                    int r0 = wm * 64 + mt * 16 + gid;
                    a[mt][0] = A[r0 * DN_STRIDE + k0 + tig];
                    a[mt][1] = A[(r0 + 8) * DN_STRIDE + k0 + tig];
                    a[mt][2] = A[r0 * DN_STRIDE + k0 + tig + 4];
                    a[mt][3] = A[(r0 + 8) * DN_STRIDE + k0 + tig + 4];
                }
                #pragma unroll
                for (int nt = 0; nt < 4; nt++) {
                    int nb = wn * 32 + nt * 8 + gid;
                    uint32_t b0 = W[nb * DN_STRIDE + k0 + tig];
                    uint32_t b1 = W[nb * DN_STRIDE + k0 + tig + 4];
                    #pragma unroll
                    for (int mt = 0; mt < 4; mt++)
                        mma_tf32(acc[mt][nt], a[mt], b0, b1);
                }
            }
        };

        const int NC = M / 32;   // 16
        ldc(0); sts(0);
        __syncthreads();
        for (int c = 0; c < NC; c++) {
            int s = c & 1;
            if (c + 1 < NC) ldc(c + 1);
            compute(s);
            __syncthreads();
            if (c + 1 < NC) { sts(s ^ 1); __syncthreads(); }
        }

        #pragma unroll
        for (int mt = 0; mt < 4; mt++) {
            #pragma unroll
            for (int rh = 0; rh < 2; rh++) {
                int r = wm * 64 + mt * 16 + gid + rh * 8;
                int aid = said_s[r];
                if (aid < 0) continue;
                float* op = g_part + (size_t)aid * H + h0 + wn * 32;
                #pragma unroll
                for (int nt = 0; nt < 4; nt++) {
                    float2 o;
                    o.x = acc[mt][nt][rh * 2 + 0];
                    o.y = acc[mt][nt][rh * 2 + 1];
                    *(float2*)(op + nt * 8 + tig * 2) = o;
                }
            }
        }
    }
}

// ------------------------- final reduce ------------------------------------
__global__ void reduce_kernel(float* __restrict__ out) {
    int i = blockIdx.x * 256 + threadIdx.x;
    int t = i >> 8;
    int h4 = i & 255;
    const float4* p = (const float4*)(g_part + (size_t)t * 4 * H) + h4;
    float4 a = p[0], b = p[256], c = p[512], d = p[768];
    float4 o;
    o.x = a.x + b.x + c.x + d.x;
    o.y = a.y + b.y + c.y + d.y;
    o.z = a.z + b.z + c.z + d.z;
    o.w = a.w + b.w + c.w + d.w;
    ((float4*)out)[i] = o;
}

// ------------------------- launcher ----------------------------------------
extern "C" void kernel_launch(void* const* d_in, const int* in_sizes, int n_in,
                              void* d_out, int out_size) {
    const float* x      = (const float*)d_in[0];
    const float* gate_w = (const float*)d_in[1];
    const float* w_gate = (const float*)d_in[2];
    const float* w_up   = (const float*)d_in[3];
    const float* w_down = (const float*)d_in[4];
    float* out = (float*)d_out;

    cudaFuncSetAttribute(gateup_mma, cudaFuncAttributeMaxDynamicSharedMemorySize, GU_SMEMB);
    cudaFuncSetAttribute(down_mma,   cudaFuncAttributeMaxDynamicSharedMemorySize, DN_SMEMB);

    zero_counts<<<1, 32>>>();
    router_kernel<<<T, 128>>>(x, gate_w);
    scan_kernel<<<1, 32>>>();
    gateup_mma<<<296, 256, GU_SMEMB>>>(x, w_gate, w_up);
    down_mma<<<296, 256, DN_SMEMB>>>(w_down);
    reduce_kernel<<<T * H / 4 / 256, 256>>>(out);
}

// round 9
// speedup vs baseline: 1.8714x; 1.3380x over previous
#include <cuda_runtime.h>
#include <cuda_fp16.h>
#include <math.h>
#include <stdint.h>

#define T 2048
#define H 1024
#define M 512
#define E 32
#define TOPK 4
#define NROWS (T * TOPK)
#define PROWS (NROWS + 128)

// ------------------------- static device scratch ---------------------------
__device__ int      g_count[E];
__device__ int      g_off[E];
__device__ int      g_typre[E + 1];
__device__ int      g_tok[E * T];
__device__ float    g_wt[E * T];
__device__ uint32_t g_hbufw[(size_t)PROWS * M / 2];   // half2 words
__device__ float    g_part[(size_t)NROWS * H];

// ------------------------- helpers -----------------------------------------
__device__ __forceinline__ uint32_t smem_u32(const void* p) {
    return (uint32_t)__cvta_generic_to_shared(p);
}
__device__ __forceinline__ uint32_t f2h2(float a, float b) {
    uint32_t r;
    asm("cvt.rn.f16x2.f32 %0, %1, %2;" : "=r"(r) : "f"(b), "f"(a));
    return r;
}
__device__ __forceinline__ uint4 pack4(float4 a, float4 b) {
    uint4 o;
    o.x = f2h2(a.x, a.y); o.y = f2h2(a.z, a.w);
    o.z = f2h2(b.x, b.y); o.w = f2h2(b.z, b.w);
    return o;
}
__device__ __forceinline__ void ldm4(uint32_t* r, uint32_t addr) {
    asm volatile("ldmatrix.sync.aligned.m8n8.x4.shared.b16 {%0,%1,%2,%3}, [%4];"
        : "=r"(r[0]), "=r"(r[1]), "=r"(r[2]), "=r"(r[3]) : "r"(addr));
}
__device__ __forceinline__ void mma_f16(float* c, const uint32_t* a, uint32_t b0, uint32_t b1) {
    asm volatile("mma.sync.aligned.m16n8k16.row.col.f32.f16.f16.f32 "
        "{%0,%1,%2,%3}, {%4,%5,%6,%7}, {%8,%9}, {%0,%1,%2,%3};"
        : "+f"(c[0]), "+f"(c[1]), "+f"(c[2]), "+f"(c[3])
        : "r"(a[0]), "r"(a[1]), "r"(a[2]), "r"(a[3]), "r"(b0), "r"(b1));
}

// smem row geometry: k32 chunk = 16 half2 words + 4 pad = 20 words = 80 bytes
#define RWORDS 20
#define RBYTES 80

// ------------------------- small kernels -----------------------------------
__global__ void zero_counts() { if (threadIdx.x < E) g_count[threadIdx.x] = 0; }

__global__ void router_kernel(const float* __restrict__ x,
                              const float* __restrict__ gate_w) {
    __shared__ float xs[H];
    __shared__ float logits[E];
    int t = blockIdx.x;
    const float* xr = x + (size_t)t * H;
    for (int i = threadIdx.x; i < H; i += blockDim.x) xs[i] = xr[i];
    __syncthreads();
    int warp = threadIdx.x >> 5, lane = threadIdx.x & 31;
    for (int e = warp; e < E; e += 4) {
        const float* w = gate_w + (size_t)e * H;
        float s = 0.f;
        for (int i = lane; i < H; i += 32) s += xs[i] * w[i];
        #pragma unroll
        for (int o = 16; o > 0; o >>= 1) s += __shfl_xor_sync(0xffffffffu, s, o);
        if (lane == 0) logits[e] = s;
    }
    __syncthreads();
    if (threadIdx.x == 0) {
        int ids[TOPK]; float vals[TOPK];
        unsigned used = 0;
        for (int k = 0; k < TOPK; k++) {
            float best = -INFINITY; int bi = 0;
            for (int e = 0; e < E; e++)
                if (!((used >> e) & 1u) && logits[e] > best) { best = logits[e]; bi = e; }
            used |= (1u << bi); ids[k] = bi; vals[k] = best;
        }
        float mx = vals[0], se = 0.f, w4[TOPK];
        for (int k = 0; k < TOPK; k++) { w4[k] = expf(vals[k] - mx); se += w4[k]; }
        float inv = 1.0f / se;
        for (int k = 0; k < TOPK; k++) {
            int e = ids[k];
            int pos = atomicAdd(&g_count[e], 1);
            g_tok[e * T + pos] = t * TOPK + k;
            g_wt[e * T + pos] = w4[k] * inv;
        }
    }
}

__global__ void scan_kernel() {
    int lane = threadIdx.x;
    int c = g_count[lane];
    int ex = c;
    #pragma unroll
    for (int o = 1; o < 32; o <<= 1) {
        int v = __shfl_up_sync(0xffffffffu, ex, o);
        if (lane >= o) ex += v;
    }
    g_off[lane] = ex - c;
    int ty = (c + 127) >> 7;
    int tp = ty;
    #pragma unroll
    for (int o = 1; o < 32; o <<= 1) {
        int v = __shfl_up_sync(0xffffffffu, tp, o);
        if (lane >= o) tp += v;
    }
    g_typre[lane] = tp - ty;
    if (lane == 31) g_typre[E] = tp;
}

// ------------------------- gate/up fp16 mma GEMM ---------------------------
// persistent; 256 threads, warps 4x2; block 128 rows x 64 m-cols;
// warp tile 32x32 carrying BOTH gate and up; K chunk 32
#define GU_STAGEW 5120
#define GU_SMEMB  (2 * GU_STAGEW * 4)      // 40960 bytes

__global__ void __launch_bounds__(256, 2)
gateup_mma(const float* __restrict__ x,
           const float* __restrict__ wg, const float* __restrict__ wu) {
    extern __shared__ uint32_t sm[];
    __shared__ int   styp[E + 1];
    __shared__ int   said_s[128];
    __shared__ float swt_s[128];

    int tid = threadIdx.x, lane = tid & 31, wid = tid >> 5;
    int gid = lane >> 2, tig = lane & 3;
    int wm = wid & 3, wn = wid >> 2;

    if (tid <= E) styp[tid] = g_typre[tid];
    __syncthreads();
    int totalW = styp[E] * 8;

    uint32_t sbase = smem_u32(sm);
    int a_ro = lane & 15;
    int a_kw = (lane >> 4) * 16;             // bytes
    uint32_t adrA0 = sbase + (uint32_t)(wm * 32 + a_ro) * RBYTES + a_kw;
    uint32_t adrA1 = adrA0 + 16 * RBYTES;
    int b_ro = (lane & 7) + ((lane & 16) >> 1);
    int b_kw = (lane & 8) ? 16 : 0;
    uint32_t adrG0 = sbase + 128 * RBYTES + (uint32_t)(wn * 32 + b_ro) * RBYTES + b_kw;
    uint32_t adrG1 = adrG0 + 16 * RBYTES;
    uint32_t adrU0 = adrG0 + 64 * RBYTES;
    uint32_t adrU1 = adrU0 + 16 * RBYTES;

    int arow = tid >> 1, ah = tid & 1;       // A: 128 rows, 2 halves of k32
    int grow = tid >> 2, gq = tid & 3;       // G/U: 64 rows, 4 quarters

    for (int w = blockIdx.x; w < totalW; w += gridDim.x) {
        int ytl = w >> 3, xt = w & 7;
        int e = 0;
        while (styp[e + 1] <= ytl) e++;
        int t0 = (ytl - styp[e]) * 128;
        int m0 = xt * 64;
        int n  = g_count[e];
        int gbase = g_off[e] + t0;

        __syncthreads();
        if (tid < 128) {
            int slot = t0 + tid;
            bool v = slot < n;
            said_s[tid] = v ? g_tok[e * T + slot] : -1;
            swt_s[tid]  = v ? g_wt[e * T + slot] : 0.f;
        }
        __syncthreads();
        int aid = said_s[arow];

        const float* wgb = wg + ((size_t)e * M + m0) * H;
        const float* wub = wu + ((size_t)e * M + m0) * H;
        const float* ap  = (aid >= 0) ? x + (size_t)(aid >> 2) * H + ah * 16 : nullptr;
        const float* gp0 = wgb + (size_t)grow * H + gq * 8;
        const float* up0 = wub + (size_t)grow * H + gq * 8;

        float accG[2][4][4], accU[2][4][4];
        #pragma unroll
        for (int i = 0; i < 2; i++)
            #pragma unroll
            for (int j = 0; j < 4; j++)
                #pragma unroll
                for (int q = 0; q < 4; q++) { accG[i][j][q] = 0.f; accU[i][j][q] = 0.f; }

        uint4 qa0, qa1, qg, qu;
        auto ldc = [&](int c) {
            int ko = c * 32;
            if (ap) {
                float4 f0 = *(const float4*)(ap + ko);
                float4 f1 = *(const float4*)(ap + ko + 4);
                float4 f2 = *(const float4*)(ap + ko + 8);
                float4 f3 = *(const float4*)(ap + ko + 12);
                qa0 = pack4(f0, f1); qa1 = pack4(f2, f3);
            } else {
                qa0 = make_uint4(0, 0, 0, 0); qa1 = qa0;
            }
            float4 g0 = *(const float4*)(gp0 + ko);
            float4 g1 = *(const float4*)(gp0 + ko + 4);
            qg = pack4(g0, g1);
            float4 u0 = *(const float4*)(up0 + ko);
            float4 u1 = *(const float4*)(up0 + ko + 4);
            qu = pack4(u0, u1);
        };
        auto sts = [&](int s) {
            uint32_t* st = sm + s * GU_STAGEW;
            uint32_t* A = st;
            uint32_t* G = st + 128 * RWORDS;
            uint32_t* U = st + 192 * RWORDS;
            *(uint4*)(A + arow * RWORDS + ah * 8)     = qa0;
            *(uint4*)(A + arow * RWORDS + ah * 8 + 4) = qa1;
            *(uint4*)(G + grow * RWORDS + gq * 4)     = qg;
            *(uint4*)(U + grow * RWORDS + gq * 4)     = qu;
        };
        auto compute = [&](int s) {
            uint32_t so = (uint32_t)s * (GU_STAGEW * 4);
            #pragma unroll
            for (int sub = 0; sub < 2; sub++) {
                uint32_t soo = so + sub * 32;
                uint32_t a0[4], a1[4], g0[4], g1[4], u0[4], u1[4];
                ldm4(a0, adrA0 + soo); ldm4(a1, adrA1 + soo);
                ldm4(g0, adrG0 + soo); ldm4(g1, adrG1 + soo);
                ldm4(u0, adrU0 + soo); ldm4(u1, adrU1 + soo);
                #pragma unroll
                for (int p = 0; p < 2; p++) {
                    const uint32_t* gg = p ? g1 : g0;
                    const uint32_t* uu = p ? u1 : u0;
                    #pragma unroll
                    for (int q = 0; q < 2; q++) {
                        int nt = p * 2 + q;
                        mma_f16(accG[0][nt], a0, gg[q * 2], gg[q * 2 + 1]);
                        mma_f16(accG[1][nt], a1, gg[q * 2], gg[q * 2 + 1]);
                        mma_f16(accU[0][nt], a0, uu[q * 2], uu[q * 2 + 1]);
                        mma_f16(accU[1][nt], a1, uu[q * 2], uu[q * 2 + 1]);
                    }
                }
            }
        };

        const int NC = H / 32;   // 32
        ldc(0); sts(0);
        __syncthreads();
        for (int c = 0; c < NC; c++) {
            int s = c & 1;
            if (c + 1 < NC) ldc(c + 1);
            compute(s);
            __syncthreads();
            if (c + 1 < NC) { sts(s ^ 1); __syncthreads(); }
        }

        // epilogue: h = silu(gate)*up*route_w -> half2 words
        #pragma unroll
        for (int mt = 0; mt < 2; mt++) {
            #pragma unroll
            for (int rh = 0; rh < 2; rh++) {
                int r = wm * 32 + mt * 16 + gid + rh * 8;
                int said = said_s[r];
                if (said < 0) continue;
                float wv = swt_s[r];
                uint32_t* hp = g_hbufw + (size_t)(gbase + r) * (M / 2)
                             + ((m0 + wn * 32) >> 1) + tig;
                #pragma unroll
                for (int nt = 0; nt < 4; nt++) {
                    float g0 = accG[mt][nt][rh * 2 + 0];
                    float g1 = accG[mt][nt][rh * 2 + 1];
                    float u0 = accU[mt][nt][rh * 2 + 0];
                    float u1 = accU[mt][nt][rh * 2 + 1];
                    float o0 = (g0 / (1.f + __expf(-g0))) * u0 * wv;
                    float o1 = (g1 / (1.f + __expf(-g1))) * u1 * wv;
                    hp[nt * 4] = f2h2(o0, o1);
                }
            }
        }
    }
}

// ------------------------- down fp16 mma GEMM ------------------------------
// persistent; 256 threads, warps 2x4; block 128 rows x 128 h-cols; warp 64x32
#define DN_STAGEW 5120
#define DN_SMEMB  (2 * DN_STAGEW * 4)      // 40960 bytes

__global__ void __launch_bounds__(256, 2)
down_mma(const float* __restrict__ wd) {
    extern __shared__ uint32_t sm[];
    __shared__ int styp[E + 1];
    __shared__ int said_s[128];

    int tid = threadIdx.x, lane = tid & 31, wid = tid >> 5;
    int gid = lane >> 2, tig = lane & 3;
    int wm = wid & 1, wn = wid >> 1;

    if (tid <= E) styp[tid] = g_typre[tid];
    __syncthreads();
    int totalW = styp[E] * 8;

    uint32_t sbase = smem_u32(sm);
    int a_ro = lane & 15;
    int a_kw = (lane >> 4) * 16;
    uint32_t adrA[4];
    #pragma unroll
    for (int mt = 0; mt < 4; mt++)
        adrA[mt] = sbase + (uint32_t)(wm * 64 + mt * 16 + a_ro) * RBYTES + a_kw;
    int b_ro = (lane & 7) + ((lane & 16) >> 1);
    int b_kw = (lane & 8) ? 16 : 0;
    uint32_t adrW0 = sbase + 128 * RBYTES + (uint32_t)(wn * 32 + b_ro) * RBYTES + b_kw;
    uint32_t adrW1 = adrW0 + 16 * RBYTES;

    int arow = tid >> 1, ah = tid & 1;

    for (int w = blockIdx.x; w < totalW; w += gridDim.x) {
        int ytl = w >> 3, xt = w & 7;
        int e = 0;
        while (styp[e + 1] <= ytl) e++;
        int t0 = (ytl - styp[e]) * 128;
        int h0 = xt * 128;
        int n  = g_count[e];
        int gbase = g_off[e] + t0;

        __syncthreads();
        if (tid < 128) {
            int slot = t0 + tid;
            said_s[tid] = (slot < n) ? g_tok[e * T + slot] : -1;
        }
        __syncthreads();

        // A rows are half2 words: 16 words per k32 chunk; thread ah handles
        // words [ah*8, ah*8+8) of each chunk.
        const uint32_t* abw = g_hbufw + (size_t)(gbase + arow) * (M / 2) + ah * 8;
        const float*    wp  = wd + ((size_t)e * H + h0 + arow) * M + ah * 16;

        float acc[4][4][4];
        #pragma unroll
        for (int i = 0; i < 4; i++)
            #pragma unroll
            for (int j = 0; j < 4; j++)
                #pragma unroll
                for (int q = 0; q < 4; q++) acc[i][j][q] = 0.f;

        uint4 qa0, qa1, qw0, qw1;
        auto ldc = [&](int c) {
            qa0 = *(const uint4*)(abw + c * 16);
            qa1 = *(const uint4*)(abw + c * 16 + 4);
            float4 f0 = *(const float4*)(wp + c * 32);
            float4 f1 = *(const float4*)(wp + c * 32 + 4);
            float4 f2 = *(const float4*)(wp + c * 32 + 8);
            float4 f3 = *(const float4*)(wp + c * 32 + 12);
            qw0 = pack4(f0, f1); qw1 = pack4(f2, f3);
        };
        auto sts = [&](int s) {
            uint32_t* st = sm + s * DN_STAGEW;
            uint32_t* A = st;
            uint32_t* W = st + 128 * RWORDS;
            *(uint4*)(A + arow * RWORDS + ah * 8)     = qa0;
            *(uint4*)(A + arow * RWORDS + ah * 8 + 4) = qa1;
            *(uint4*)(W + arow * RWORDS + ah * 8)     = qw0;
            *(uint4*)(W + arow * RWORDS + ah * 8 + 4) = qw1;
        };
        auto compute = [&](int s) {
            uint32_t so = (uint32_t)s * (DN_STAGEW * 4);
            #pragma unroll
            for (int sub = 0; sub < 2; sub++) {
                uint32_t soo = so + sub * 32;
                uint32_t a[4][4], w0[4], w1[4];
                #pragma unroll
                for (int mt = 0; mt < 4; mt++) ldm4(a[mt], adrA[mt] + soo);
                ldm4(w0, adrW0 + soo); ldm4(w1, adrW1 + soo);
                #pragma unroll
                for (int p = 0; p < 2; p++) {
                    const uint32_t* ww = p ? w1 : w0;
                    #pragma unroll
                    for (int q = 0; q < 2; q++) {
                        int nt = p * 2 + q;
                        #pragma unroll
                        for (int mt = 0; mt < 4; mt++)
                            mma_f16(acc[mt][nt], a[mt], ww[q * 2], ww[q * 2 + 1]);
                    }
                }
            }
        };

        const int NC = M / 32;   // 16
        ldc(0); sts(0);
        __syncthreads();
        for (int c = 0; c < NC; c++) {
            int s = c & 1;
            if (c + 1 < NC) ldc(c + 1);
            compute(s);
            __syncthreads();
            if (c + 1 < NC) { sts(s ^ 1); __syncthreads(); }
        }

        #pragma unroll
        for (int mt = 0; mt < 4; mt++) {
            #pragma unroll
            for (int rh = 0; rh < 2; rh++) {
                int r = wm * 64 + mt * 16 + gid + rh * 8;
                int aid = said_s[r];
                if (aid < 0) continue;
                float* op = g_part + (size_t)aid * H + h0 + wn * 32;
                #pragma unroll
                for (int nt = 0; nt < 4; nt++) {
                    float2 o;
                    o.x = acc[mt][nt][rh * 2 + 0];
                    o.y = acc[mt][nt][rh * 2 + 1];
                    *(float2*)(op + nt * 8 + tig * 2) = o;
                }
            }
        }
    }
}

// ------------------------- final reduce ------------------------------------
__global__ void reduce_kernel(float* __restrict__ out) {
    int i = blockIdx.x * 256 + threadIdx.x;
    int t = i >> 8;
    int h4 = i & 255;
    const float4* p = (const float4*)(g_part + (size_t)t * 4 * H) + h4;
    float4 a = p[0], b = p[256], c = p[512], d = p[768];
    float4 o;
    o.x = a.x + b.x + c.x + d.x;
    o.y = a.y + b.y + c.y + d.y;
    o.z = a.z + b.z + c.z + d.z;
    o.w = a.w + b.w + c.w + d.w;
    ((float4*)out)[i] = o;
}

// ------------------------- launcher ----------------------------------------
extern "C" void kernel_launch(void* const* d_in, const int* in_sizes, int n_in,
                              void* d_out, int out_size) {
    const float* x      = (const float*)d_in[0];
    const float* gate_w = (const float*)d_in[1];
    const float* w_gate = (const float*)d_in[2];
    const float* w_up   = (const float*)d_in[3];
    const float* w_down = (const float*)d_in[4];
    float* out = (float*)d_out;

    cudaFuncSetAttribute(gateup_mma, cudaFuncAttributeMaxDynamicSharedMemorySize, GU_SMEMB);
    cudaFuncSetAttribute(down_mma,   cudaFuncAttributeMaxDynamicSharedMemorySize, DN_SMEMB);

    zero_counts<<<1, 32>>>();
    router_kernel<<<T, 128>>>(x, gate_w);
    scan_kernel<<<1, 32>>>();
    gateup_mma<<<296, 256, GU_SMEMB>>>(x, w_gate, w_up);
    down_mma<<<296, 256, DN_SMEMB>>>(w_down);
    reduce_kernel<<<T * H / 4 / 256, 256>>>(out);
}